// round 4
// baseline (speedup 1.0000x reference)
#include <cuda_runtime.h>

// ---------------------------------------------------------------------------
// ConvAttention: q=conv2d(input)*0.5, k=conv2d(memory), v=conv3d(memory),
// per-(b,head) channel-gram softmax attention, out = attn @ v.
// B=8, Cin=64, Cout=128, L=18 (v: 16), H=W=32, heads=2 split along depth.
// Fully fp32; convs use packed fma.rn.f32x2 (2 FMAs/lane/issue on sm_103a),
// with register-prefetch software pipelining on the smem staging.
// ---------------------------------------------------------------------------

#define BB   8
#define CIN  64
#define COUT 128
#define LIN  18
#define LV   16
#define NPX  1024   // 32*32

// -------------------- scratch (device globals; no allocs) ------------------
__device__ float g_Q[BB*COUT*LIN*NPX];          // 75.5 MB
__device__ float g_K[BB*COUT*LIN*NPX];          // 75.5 MB
__device__ float g_V[BB*COUT*LV*NPX];           // 67 MB
__device__ float g_wqT[CIN*9*COUT];             // [ci][tap][co]
__device__ float g_wkT[CIN*9*COUT];
__device__ float g_wvT[3*CIN*9*COUT];           // [kd][ci][tap][co]
__device__ float g_part[16*9*COUT*COUT];        // gram K-split partials
__device__ float g_attnT[16*COUT*COUT];         // attn transposed: [bn][m][c]

// -------------------- f32x2 helpers ----------------------------------------
static __device__ __forceinline__ unsigned long long pack2(float lo, float hi){
    unsigned long long r;
    asm("mov.b64 %0, {%1, %2};" : "=l"(r) : "f"(lo), "f"(hi));
    return r;
}
static __device__ __forceinline__ unsigned long long dup2(float v){
    unsigned long long r;
    asm("mov.b64 %0, {%1, %1};" : "=l"(r) : "f"(v));
    return r;
}
static __device__ __forceinline__ void unpack2(unsigned long long v, float& lo, float& hi){
    asm("mov.b64 {%0, %1}, %2;" : "=f"(lo), "=f"(hi) : "l"(v));
}
static __device__ __forceinline__ void fma2(unsigned long long& acc,
                                            unsigned long long a,
                                            unsigned long long b){
    asm("fma.rn.f32x2 %0, %1, %2, %0;" : "+l"(acc) : "l"(a), "l"(b));
}

// -------------------- weight transpose -------------------------------------
// wT[kd][ci][tap][co] <- w[co][ci][kd][ky][kx]; makes conv smem staging a
// straight coalesced copy (conflict-free STS, broadcast LDS in mainloop).
__global__ void transpose_w(const float* __restrict__ wq,
                            const float* __restrict__ wk,
                            const float* __restrict__ wv){
    int i = blockIdx.x * 256 + threadIdx.x;
    if (i < CIN*9*COUT){
        int ci = i / 1152; int rem = i - ci*1152;
        int tap = rem >> 7; int co = rem & 127;
        g_wqT[i] = wq[(co*CIN + ci)*9 + tap];
        g_wkT[i] = wk[(co*CIN + ci)*9 + tap];
    }
    if (i < 3*CIN*9*COUT){
        int kd = i / 73728; int rr = i - kd*73728;
        int ci = rr / 1152; int rem = rr - ci*1152;
        int tap = rem >> 7; int co = rem & 127;
        g_wvT[i] = wv[((co*CIN + ci)*3 + kd)*9 + tap];
    }
}

// -------------------- conv kernel ------------------------------------------
// Block: 512 threads computing all 128 co for an 8-row x 32-col pixel tile
// of one (b,l). Per thread: 16 co (8 f32x2 pairs) x 4 px register tile.
// KD=1 -> Q/K conv fused in one launch (grid.z: [0,8)=Q, [8,16)=K);
// KD=3 -> V conv (depth-valid).
// Staging is software-pipelined: stage s+1 is prefetched into registers while
// compute of stage s runs; only STS + barriers remain inside the sync window.
template<int KD>
__global__ __launch_bounds__(512, 1)
void conv_kernel(const float* __restrict__ srcA, const float* __restrict__ srcB,
                 const float* __restrict__ biasA, const float* __restrict__ biasB)
{
    int zb = blockIdx.z;
    int mode = (KD == 3) ? 2 : (zb >> 3);      // 0=Q, 1=K, 2=V
    int b    = (KD == 3) ? zb : (zb & 7);

    const float* src  = (mode == 0) ? srcA  : srcB;
    const float* bias = (mode == 0) ? biasA : biasB;
    const float* wT   = (mode == 0) ? g_wqT : (mode == 1) ? g_wkT : g_wvT;
    float* dst        = (mode == 0) ? g_Q   : (mode == 1) ? g_K   : g_V;
    const float scale = (mode == 0) ? 0.5f : 1.0f;
    const int Lout    = (KD == 3) ? LV : LIN;
    const int S       = 8 * KD;                // stages: (CIN/8) * KD

    __shared__ __align__(16) float w_s[8*9*128];   // [ci][tap][co]  36864 B
    __shared__ __align__(16) float in_s[8*10*35];  // [ci][r][cx]    11200 B

    int rt = blockIdx.x, l = blockIdx.y;
    int r0 = rt * 8;
    int t  = threadIdx.x;
    int pg = t & 63, cg = t >> 6;
    int row = pg >> 3, col4 = (pg & 7) * 4;
    int co0 = cg * 16;

    unsigned long long acc[8][4];
    #pragma unroll
    for (int p = 0; p < 8; p++){
        unsigned long long pk = pack2(bias[co0 + 2*p], bias[co0 + 2*p + 1]);
        acc[p][0] = pk; acc[p][1] = pk; acc[p][2] = pk; acc[p][3] = pk;
    }

    float  in_r[6];   // input prefetch: idx = t + i*512 < 2720
    float4 w_r[5];    // weight prefetch: idx = t + i*512 < 2304 (float4 units)

    // ---- stage prefetch: global -> registers -------------------------------
    auto load_stage = [&](int s){
        int cb = s / KD;                 // channel block
        int kd = s - cb * KD;            // depth tap
        int c0 = cb * 8;
        int lin = l + kd;                // depth pad 0 (KD=1: lin==l)
        #pragma unroll
        for (int i = 0; i < 6; i++){
            int idx = t + i*512;
            float v = 0.f;
            if (idx < 2720){
                int ci = idx / 340; int rem = idx - ci*340;
                int r  = rem / 34;  int cx  = rem - r*34;
                int y = r0 + r - 1, x = cx - 1;
                if (y >= 0 && y < 32 && x >= 0 && x < 32)
                    v = src[(((b*CIN + c0 + ci)*LIN + lin) << 10) + (y << 5) + x];
            }
            in_r[i] = v;
        }
        const float4* wsrc4 = (const float4*)(wT + (kd*CIN + c0) * 1152);
        #pragma unroll
        for (int i = 0; i < 5; i++){
            int idx = t + i*512;
            if (idx < 2304) w_r[i] = wsrc4[idx];
        }
    };
    // ---- stage commit: registers -> shared ---------------------------------
    auto store_stage = [&](){
        #pragma unroll
        for (int i = 0; i < 6; i++){
            int idx = t + i*512;
            if (idx < 2720){
                int ci = idx / 340; int rem = idx - ci*340;
                int r  = rem / 34;  int cx  = rem - r*34;
                in_s[(ci*10 + r)*35 + cx] = in_r[i];
            }
        }
        float4* wdst4 = (float4*)w_s;
        #pragma unroll
        for (int i = 0; i < 5; i++){
            int idx = t + i*512;
            if (idx < 2304) wdst4[idx] = w_r[i];
        }
    };

    load_stage(0);
    for (int s = 0; s < S; s++){
        __syncthreads();                 // previous compute done reading smem
        store_stage();
        __syncthreads();                 // stage visible to all
        if (s + 1 < S) load_stage(s + 1);   // LDGs overlap with compute below

        for (int ci = 0; ci < 8; ci++){
            const float* wrow = &w_s[ci * 1152];
            #pragma unroll
            for (int ky = 0; ky < 3; ky++){
                const float* irow = &in_s[(ci*10 + row + ky)*35 + col4];
                unsigned long long dd[6];
                dd[0] = dup2(irow[0]); dd[1] = dup2(irow[1]);
                dd[2] = dup2(irow[2]); dd[3] = dup2(irow[3]);
                dd[4] = dup2(irow[4]); dd[5] = dup2(irow[5]);
                #pragma unroll
                for (int kx = 0; kx < 3; kx++){
                    const unsigned long long* wp =
                        (const unsigned long long*)&wrow[(ky*3 + kx)*128 + co0];
                    #pragma unroll
                    for (int p = 0; p < 8; p++){
                        unsigned long long w2 = wp[p];
                        fma2(acc[p][0], w2, dd[kx + 0]);
                        fma2(acc[p][1], w2, dd[kx + 1]);
                        fma2(acc[p][2], w2, dd[kx + 2]);
                        fma2(acc[p][3], w2, dd[kx + 3]);
                    }
                }
            }
        }
    }

    // epilogue: unpack co-pairs, apply scale (bias included pre-scale, matching
    // (conv+b)*scale), vectorized 16B stores.
    #pragma unroll
    for (int p = 0; p < 8; p++){
        float lo0,hi0,lo1,hi1,lo2,hi2,lo3,hi3;
        unpack2(acc[p][0], lo0, hi0);
        unpack2(acc[p][1], lo1, hi1);
        unpack2(acc[p][2], lo2, hi2);
        unpack2(acc[p][3], lo3, hi3);
        int co = co0 + 2*p;
        int base = (((b*COUT + co)*Lout + l) << 10) + ((r0 + row) << 5) + col4;
        float4 o0 = make_float4(lo0*scale, lo1*scale, lo2*scale, lo3*scale);
        float4 o1 = make_float4(hi0*scale, hi1*scale, hi2*scale, hi3*scale);
        *(float4*)(dst + base) = o0;
        *(float4*)(dst + base + (Lout << 10)) = o1;
    }
}

// -------------------- gram (logit) kernel ----------------------------------
// logit[bn][c][m] = sum_i q_bn[c][i] * k_bn[m][i], i over 9216.
// K-split by depth slice (9 per head) -> 144 blocks, partials reduced later.
__global__ __launch_bounds__(256)
void gram_kernel(){
    int ds = blockIdx.x, n = blockIdx.y, b = blockIdx.z;
    int bn = b*2 + n;
    const float* qb = g_Q + (((b*COUT)*LIN + n*9 + ds) << 10);
    const float* kb = g_K + (((b*COUT)*LIN + n*9 + ds) << 10);

    __shared__ float q_s[32*129];   // [i_local][c], pad 129 -> conflict-free STS
    __shared__ float k_s[32*129];

    int t = threadIdx.x;
    int tc = t & 15, tm = t >> 4;
    float acc[8][8];
    #pragma unroll
    for (int x = 0; x < 8; x++)
        #pragma unroll
        for (int y = 0; y < 8; y++) acc[x][y] = 0.f;

    for (int i0 = 0; i0 < 1024; i0 += 32){
        __syncthreads();
        #pragma unroll
        for (int idx = t; idx < 4096; idx += 256){
            int c = idx >> 5, il = idx & 31;
            q_s[il*129 + c] = qb[c*(LIN*NPX) + i0 + il];
            k_s[il*129 + c] = kb[c*(LIN*NPX) + i0 + il];
        }
        __syncthreads();
        for (int il = 0; il < 32; il++){
            float a[8], bv[8];
            #pragma unroll
            for (int j = 0; j < 8; j++) a[j]  = q_s[il*129 + tc*8 + j];
            #pragma unroll
            for (int j = 0; j < 8; j++) bv[j] = k_s[il*129 + tm*8 + j];
            #pragma unroll
            for (int x = 0; x < 8; x++)
                #pragma unroll
                for (int y = 0; y < 8; y++)
                    acc[x][y] += a[x] * bv[y];
        }
    }
    float* pp = g_part + (bn*9 + ds) * (COUT*COUT);
    #pragma unroll
    for (int x = 0; x < 8; x++)
        #pragma unroll
        for (int y = 0; y < 8; y++)
            pp[(tc*8 + x)*COUT + tm*8 + y] = acc[x][y];
}

// -------------------- softmax ----------------------------------------------
// One block per (bn, c) row: reduce 9 partials, max-subtract softmax over m,
// store transposed attn[bn][m][c] so the output GEMM stages coalesced.
__global__ void softmax_kernel(){
    int bid = blockIdx.x;
    int bn = bid >> 7, c = bid & 127;
    int m = threadIdx.x;
    const float* pp = g_part + bn*9*(COUT*COUT) + c*COUT + m;
    float s = 0.f;
    #pragma unroll
    for (int ds = 0; ds < 9; ds++) s += pp[ds*(COUT*COUT)];

    __shared__ float red[128];
    red[m] = s; __syncthreads();
    for (int off = 64; off > 0; off >>= 1){
        if (m < off) red[m] = fmaxf(red[m], red[m + off]);
        __syncthreads();
    }
    float mx = red[0]; __syncthreads();
    float e = expf(s - mx);
    red[m] = e; __syncthreads();
    for (int off = 64; off > 0; off >>= 1){
        if (m < off) red[m] += red[m + off];
        __syncthreads();
    }
    float S = red[0];
    g_attnT[(bn*COUT + m)*COUT + c] = e / S;
}

// -------------------- output GEMM ------------------------------------------
// out[bn][c][j] = sum_m attn[bn][c][m] * v_bn[m][j], j over 8192 (=8 depth*1024).
// Writes final layout directly: out[b][c][n*8 + d][h][w].
__global__ __launch_bounds__(256)
void out_kernel(float* __restrict__ out){
    int jt = blockIdx.x, n = blockIdx.y, b = blockIdx.z;
    int bn = b*2 + n;
    const float* at = g_attnT + bn*(COUT*COUT);            // [m][c]
    const float* vb = g_V + ((b*COUT*LV + n*8) << 10);     // [m][j], m-stride 16384

    __shared__ float a_s[32*129];   // [m_local][c]
    __shared__ float v_s[32*129];   // [m_local][j_local]

    int t = threadIdx.x;
    int tj = t & 15, tc = t >> 4;
    int j0 = jt * 128;
    float acc[8][8];
    #pragma unroll
    for (int x = 0; x < 8; x++)
        #pragma unroll
        for (int y = 0; y < 8; y++) acc[x][y] = 0.f;

    for (int m0 = 0; m0 < 128; m0 += 32){
        __syncthreads();
        #pragma unroll
        for (int idx = t; idx < 4096; idx += 256){
            int il = idx >> 7, q = idx & 127;
            a_s[il*129 + q] = at[(m0 + il)*COUT + q];
            v_s[il*129 + q] = vb[(m0 + il)*(LV*NPX) + j0 + q];
        }
        __syncthreads();
        for (int il = 0; il < 32; il++){
            float a[8], bv[8];
            #pragma unroll
            for (int x = 0; x < 8; x++) a[x]  = a_s[il*129 + tc*8 + x];
            #pragma unroll
            for (int y = 0; y < 8; y++) bv[y] = v_s[il*129 + tj*8 + y];
            #pragma unroll
            for (int x = 0; x < 8; x++)
                #pragma unroll
                for (int y = 0; y < 8; y++)
                    acc[x][y] += a[x] * bv[y];
        }
    }
    #pragma unroll
    for (int x = 0; x < 8; x++){
        int c = tc*8 + x;
        int base = (((b*COUT + c)*16 + n*8) << 10) + j0 + tj*8;
        float4 o0 = make_float4(acc[x][0], acc[x][1], acc[x][2], acc[x][3]);
        float4 o1 = make_float4(acc[x][4], acc[x][5], acc[x][6], acc[x][7]);
        *(float4*)(out + base)     = o0;
        *(float4*)(out + base + 4) = o1;
    }
}

// -------------------- launch -----------------------------------------------
extern "C" void kernel_launch(void* const* d_in, const int* in_sizes, int n_in,
                              void* d_out, int out_size)
{
    const float* input  = (const float*)d_in[0];
    const float* memory = (const float*)d_in[1];
    const float* wq     = (const float*)d_in[2];
    const float* bq     = (const float*)d_in[3];
    const float* wk     = (const float*)d_in[4];
    const float* bk     = (const float*)d_in[5];
    const float* wv     = (const float*)d_in[6];
    const float* bv     = (const float*)d_in[7];
    float* out          = (float*)d_out;

    transpose_w<<<864, 256>>>(wq, wk, wv);

    // Q+K fused: grid.z [0,8)=Q(input,bq,scale .5), [8,16)=K(memory,bk)
    conv_kernel<1><<<dim3(4, LIN, 16), 512>>>(input, memory, bq, bk);
    // V conv (reads memory/bv via mode==2 path)
    conv_kernel<3><<<dim3(4, LV, BB), 512>>>(memory, memory, bv, bv);

    gram_kernel<<<dim3(9, 2, BB), 256>>>();
    softmax_kernel<<<16*128, 128>>>();
    out_kernel<<<dim3(64, 2, BB), 256>>>(out);
}

// round 13
// speedup vs baseline: 1.0110x; 1.0110x over previous
#include <cuda_runtime.h>

// ---------------------------------------------------------------------------
// ConvAttention: q=conv2d(input)*0.5, k=conv2d(memory), v=conv3d(memory),
// per-(b,head) channel-gram softmax attention, out = attn @ v.
// B=8, Cin=64, Cout=128, L=18 (v: 16), H=W=32, heads=2 split along depth.
// Fully fp32; convs use packed fma.rn.f32x2. The output GEMM is folded into
// the V conv via W'[bn] = attn[bn] @ Wv (linearity): the V conv writes d_out
// directly. V conv uses 4-row tiles (1024 blocks, 6.92 waves) to kill the
// wave-quantization tail; Q/K keep 8-row tiles (identical to prior rounds).
// ---------------------------------------------------------------------------

#define BB   8
#define CIN  64
#define COUT 128
#define LIN  18
#define LV   16
#define NPX  1024   // 32*32

typedef unsigned long long ull;

// -------------------- scratch (device globals; no allocs) ------------------
__device__ float g_Q[BB*COUT*LIN*NPX];          // 75.5 MB
__device__ float g_K[BB*COUT*LIN*NPX];          // 75.5 MB
__device__ float g_wqT[CIN*9*COUT];             // [ci][tap][co]
__device__ float g_wkT[CIN*9*COUT];
__device__ float g_wvT[3*CIN*9*COUT];           // [kd][ci][tap][m]
__device__ float g_part[16*18*COUT*COUT];       // gram K-split partials (18/bn)
__device__ float g_attn[16*COUT*COUT];          // attn [bn][c][m]
__device__ float g_wpT[16*3*CIN*9*COUT];        // W'T [bn][kd][ci][tap][c] 14.2MB
__device__ float g_bp[16*COUT];                 // b'  [bn][c]

// -------------------- f32x2 helpers ----------------------------------------
static __device__ __forceinline__ ull pack2(float lo, float hi){
    ull r; asm("mov.b64 %0, {%1, %2};" : "=l"(r) : "f"(lo), "f"(hi)); return r;
}
static __device__ __forceinline__ ull dup2(float v){
    ull r; asm("mov.b64 %0, {%1, %1};" : "=l"(r) : "f"(v)); return r;
}
static __device__ __forceinline__ void unpack2(ull v, float& lo, float& hi){
    asm("mov.b64 {%0, %1}, %2;" : "=f"(lo), "=f"(hi) : "l"(v));
}
static __device__ __forceinline__ void fma2(ull& acc, ull a, ull b){
    asm("fma.rn.f32x2 %0, %1, %2, %0;" : "+l"(acc) : "l"(a), "l"(b));
}

// -------------------- weight transpose -------------------------------------
__global__ void transpose_w(const float* __restrict__ wq,
                            const float* __restrict__ wk,
                            const float* __restrict__ wv){
    int i = blockIdx.x * 256 + threadIdx.x;
    if (i < CIN*9*COUT){
        int ci = i / 1152; int rem = i - ci*1152;
        int tap = rem >> 7; int co = rem & 127;
        g_wqT[i] = wq[(co*CIN + ci)*9 + tap];
        g_wkT[i] = wk[(co*CIN + ci)*9 + tap];
    }
    if (i < 3*CIN*9*COUT){
        int kd = i / 73728; int rr = i - kd*73728;
        int ci = rr / 1152; int rem = rr - ci*1152;
        int tap = rem >> 7; int co = rem & 127;
        g_wvT[i] = wv[((co*CIN + ci)*3 + kd)*9 + tap];
    }
}

// -------------------- conv kernel ------------------------------------------
// 512 threads; all 128 co for a ROWSx32 pixel tile of one (b,l).
// KD=1: ROWS=8, PX=4 (identical mapping to prior rounds), Q/K fused via
//       grid.z [0,8)=Q, [8,16)=K -> g_Q/g_K.
// KD=3: ROWS=4, PX=2 (1024 blocks -> 6.92 waves), attention-folded V conv
//       with weights g_wpT[bn]/bias g_bp[bn], writes outp (final layout).
// Register-prefetch pipelined staging in both cases.
template<int KD>
__global__ __launch_bounds__(512, 1)
void conv_kernel(const float* __restrict__ srcA, const float* __restrict__ srcB,
                 const float* __restrict__ biasA, const float* __restrict__ biasB,
                 float* __restrict__ outp)
{
    constexpr int ROWS  = (KD == 3) ? 4 : 8;    // pixel rows per tile
    constexpr int PX    = (KD == 3) ? 2 : 4;    // px per thread
    constexpr int HR    = ROWS + 2;             // halo rows
    constexpr int ITEMS = 8 * HR * 34;          // input stage elements
    constexpr int INR   = (ITEMS + 511) / 512;  // input prefetch regs
    constexpr int CGRP  = 32 / PX;              // col groups per row

    int zb = blockIdx.z;
    int l  = blockIdx.y;
    int mode = (KD == 3) ? 2 : (zb >> 3);      // 0=Q, 1=K, 2=V'
    int b    = (KD == 3) ? zb : (zb & 7);
    int bn   = b*2 + (l >> 3);                 // used for mode 2 only

    const float* src  = (mode == 0) ? srcA  : srcB;
    const float* bias = (mode == 0) ? biasA : (mode == 1) ? biasB
                                            : (g_bp + (bn << 7));
    const float* wT   = (mode == 0) ? g_wqT : (mode == 1) ? g_wkT
                                            : (g_wpT + bn*(3*CIN*9*COUT));
    float* dst        = (mode == 0) ? g_Q   : (mode == 1) ? g_K   : outp;
    const float scale = (mode == 0) ? 0.5f : 1.0f;
    const int Lout    = (KD == 3) ? LV : LIN;
    const int S       = 8 * KD;                // stages: (CIN/8) * KD

    __shared__ __align__(16) float w_s[8*9*128];     // [ci][tap][co]
    __shared__ __align__(16) float in_s[8*HR*35];    // [ci][r][cx]

    int rt = blockIdx.x;
    int r0 = rt * ROWS;
    int t  = threadIdx.x;
    int pg = t & 63, cg = t >> 6;
    int row  = pg / CGRP;
    int col0 = (pg % CGRP) * PX;
    int co0  = cg * 16;

    ull acc[8][PX];
    #pragma unroll
    for (int p = 0; p < 8; p++){
        ull pk = pack2(bias[co0 + 2*p], bias[co0 + 2*p + 1]);
        #pragma unroll
        for (int j = 0; j < PX; j++) acc[p][j] = pk;
    }

    float  in_r[INR];
    float4 w_r[5];    // weight prefetch: idx = t + i*512 < 2304 (float4 units)

    auto load_stage = [&](int s){
        int cb = s / KD;
        int kd = s - cb * KD;
        int c0 = cb * 8;
        int lin = l + kd;                // depth pad 0 (KD=1: lin==l)
        #pragma unroll
        for (int i = 0; i < INR; i++){
            int idx = t + i*512;
            float v = 0.f;
            if (idx < ITEMS){
                int ci = idx / (HR*34); int rem = idx - ci*(HR*34);
                int r  = rem / 34;      int cx  = rem - r*34;
                int y = r0 + r - 1, x = cx - 1;
                if (y >= 0 && y < 32 && x >= 0 && x < 32)
                    v = src[(((b*CIN + c0 + ci)*LIN + lin) << 10) + (y << 5) + x];
            }
            in_r[i] = v;
        }
        const float4* wsrc4 = (const float4*)(wT + (kd*CIN + c0) * 1152);
        #pragma unroll
        for (int i = 0; i < 5; i++){
            int idx = t + i*512;
            if (idx < 2304) w_r[i] = wsrc4[idx];
        }
    };
    auto store_stage = [&](){
        #pragma unroll
        for (int i = 0; i < INR; i++){
            int idx = t + i*512;
            if (idx < ITEMS){
                int ci = idx / (HR*34); int rem = idx - ci*(HR*34);
                int r  = rem / 34;      int cx  = rem - r*34;
                in_s[(ci*HR + r)*35 + cx] = in_r[i];
            }
        }
        float4* wdst4 = (float4*)w_s;
        #pragma unroll
        for (int i = 0; i < 5; i++){
            int idx = t + i*512;
            if (idx < 2304) wdst4[idx] = w_r[i];
        }
    };

    load_stage(0);
    for (int s = 0; s < S; s++){
        __syncthreads();
        store_stage();
        __syncthreads();
        if (s + 1 < S) load_stage(s + 1);   // LDGs overlap with compute below

        for (int ci = 0; ci < 8; ci++){
            const float* wrow = &w_s[ci * 1152];
            #pragma unroll
            for (int ky = 0; ky < 3; ky++){
                const float* irow = &in_s[(ci*HR + row + ky)*35 + col0];
                ull dd[PX + 2];
                #pragma unroll
                for (int j = 0; j < PX + 2; j++) dd[j] = dup2(irow[j]);
                #pragma unroll
                for (int kx = 0; kx < 3; kx++){
                    const ull* wp = (const ull*)&wrow[(ky*3 + kx)*128 + co0];
                    #pragma unroll
                    for (int p = 0; p < 8; p++){
                        ull w2 = wp[p];
                        #pragma unroll
                        for (int j = 0; j < PX; j++)
                            fma2(acc[p][j], w2, dd[kx + j]);
                    }
                }
            }
        }
    }

    // epilogue: unpack co-pairs, apply scale, vectorized stores.
    #pragma unroll
    for (int p = 0; p < 8; p++){
        float lo[PX], hi[PX];
        #pragma unroll
        for (int j = 0; j < PX; j++) unpack2(acc[p][j], lo[j], hi[j]);
        int co = co0 + 2*p;
        int base = (((b*COUT + co)*Lout + l) << 10) + ((r0 + row) << 5) + col0;
        if (PX == 4){
            float4 o0 = make_float4(lo[0]*scale, lo[1]*scale, lo[2]*scale, lo[3]*scale);
            float4 o1 = make_float4(hi[0]*scale, hi[1]*scale, hi[2]*scale, hi[3]*scale);
            *(float4*)(dst + base) = o0;
            *(float4*)(dst + base + (Lout << 10)) = o1;
        } else {
            float2 o0 = make_float2(lo[0]*scale, lo[1]*scale);
            float2 o1 = make_float2(hi[0]*scale, hi[1]*scale);
            *(float2*)(dst + base) = o0;
            *(float2*)(dst + base + (Lout << 10)) = o1;
        }
    }
}

// -------------------- gram (logit) kernel ----------------------------------
// logit[bn][c][m] = sum_i q[c][i]*k[m][i], i over 9216. Split 9 depth-slices
// x 2 pixel-chunks -> 288 blocks (2/SM), partials reduced in softmax.
// f32x2 accumulators along m (pairs); operand loads stay scalar LDS.
__global__ __launch_bounds__(256, 2)
void gram_kernel(){
    int bx = blockIdx.x;                 // 18 = ds*2 + ic
    int ds = bx >> 1, ic = bx & 1;
    int n = blockIdx.y, b = blockIdx.z;
    int bn = b*2 + n;
    const float* qb = g_Q + (((b*COUT)*LIN + n*9 + ds) << 10);
    const float* kb = g_K + (((b*COUT)*LIN + n*9 + ds) << 10);

    __shared__ __align__(16) float q_s[32*129];  // [i_local][c], pad 129
    __shared__ __align__(16) float k_s[32*129];

    int t = threadIdx.x;
    int tc = t & 15, tm = t >> 4;
    ull acc2[8][4];
    #pragma unroll
    for (int x = 0; x < 8; x++)
        #pragma unroll
        for (int y = 0; y < 4; y++) acc2[x][y] = 0ull;

    for (int i0 = ic*512; i0 < ic*512 + 512; i0 += 32){
        __syncthreads();
        #pragma unroll
        for (int idx = t; idx < 4096; idx += 256){
            int c = idx >> 5, il = idx & 31;
            q_s[il*129 + c] = qb[c*(LIN*NPX) + i0 + il];
            k_s[il*129 + c] = kb[c*(LIN*NPX) + i0 + il];
        }
        __syncthreads();
        for (int il = 0; il < 32; il++){
            ull ad[8], bv2[4];
            #pragma unroll
            for (int x = 0; x < 8; x++) ad[x] = dup2(q_s[il*129 + tc*8 + x]);
            #pragma unroll
            for (int y = 0; y < 4; y++)
                bv2[y] = pack2(k_s[il*129 + tm*8 + 2*y],
                               k_s[il*129 + tm*8 + 2*y + 1]);
            #pragma unroll
            for (int x = 0; x < 8; x++)
                #pragma unroll
                for (int y = 0; y < 4; y++)
                    fma2(acc2[x][y], ad[x], bv2[y]);
        }
    }
    float* pp = g_part + (bn*18 + ds*2 + ic) * (COUT*COUT);
    #pragma unroll
    for (int x = 0; x < 8; x++)
        #pragma unroll
        for (int y = 0; y < 4; y++){
            float lo, hi; unpack2(acc2[x][y], lo, hi);
            pp[(tc*8 + x)*COUT + tm*8 + 2*y]     = lo;
            pp[(tc*8 + x)*COUT + tm*8 + 2*y + 1] = hi;
        }
}

// -------------------- softmax + bias fold ----------------------------------
// One block per (bn, c): reduce 18 partials, max-subtract softmax over m,
// store attn[bn][c][m] (coalesced) and b'[bn][c] = sum_m attn*bv[m].
__global__ void softmax_kernel(const float* __restrict__ bv){
    int bid = blockIdx.x;
    int bn = bid >> 7, c = bid & 127;
    int m = threadIdx.x;
    const float* pp = g_part + bn*18*(COUT*COUT) + c*COUT + m;
    float s = 0.f;
    #pragma unroll
    for (int p = 0; p < 18; p++) s += pp[p*(COUT*COUT)];

    __shared__ float red[128];
    red[m] = s; __syncthreads();
    for (int off = 64; off > 0; off >>= 1){
        if (m < off) red[m] = fmaxf(red[m], red[m + off]);
        __syncthreads();
    }
    float mx = red[0]; __syncthreads();
    float e = expf(s - mx);
    red[m] = e; __syncthreads();
    for (int off = 64; off > 0; off >>= 1){
        if (m < off) red[m] += red[m + off];
        __syncthreads();
    }
    float S = red[0]; __syncthreads();
    float a = e / S;
    g_attn[(bn*COUT + c)*COUT + m] = a;
    red[m] = a * bv[m]; __syncthreads();
    for (int off = 64; off > 0; off >>= 1){
        if (m < off) red[m] += red[m + off];
        __syncthreads();
    }
    if (m == 0) g_bp[bn*COUT + c] = red[0];
}

// -------------------- W' prep: W'T[bn][r][c] = sum_m wvT[r][m]*attn[bn][c][m]
// r = (kd*CIN+ci)*9+tap in [0,1728). Grid (27 row-tiles of 64, 16 bn).
__global__ __launch_bounds__(256)
void prep_kernel(){
    int rt = blockIdx.x, bn = blockIdx.y;
    int r0 = rt * 64;
    int t = threadIdx.x;
    int ttr = t >> 2;          // local row 0..63
    int tq  = t & 3;           // col group of 32 c's
    const float* attn = g_attn + bn*(COUT*COUT);

    __shared__ __align__(16) float at_s[32*132]; // [ml][c], pad 132 (8B pairs)

    ull acc2[16];
    #pragma unroll
    for (int j = 0; j < 16; j++) acc2[j] = 0ull;

    int r = r0 + ttr;
    for (int m0 = 0; m0 < 128; m0 += 32){
        __syncthreads();
        #pragma unroll
        for (int idx = t; idx < 4096; idx += 256){
            int c = idx >> 5, ml = idx & 31;
            at_s[ml*132 + c] = attn[c*COUT + m0 + ml];
        }
        __syncthreads();
        #pragma unroll
        for (int ml4 = 0; ml4 < 32; ml4 += 4){
            float4 w4 = *(const float4*)&g_wvT[r*COUT + m0 + ml4];
            float wv[4] = {w4.x, w4.y, w4.z, w4.w};
            #pragma unroll
            for (int q = 0; q < 4; q++){
                ull w2 = dup2(wv[q]);
                const ull* ap = (const ull*)&at_s[(ml4 + q)*132 + tq*32];
                #pragma unroll
                for (int j = 0; j < 16; j++)
                    fma2(acc2[j], w2, ap[j]);
            }
        }
    }
    float* wp = g_wpT + bn*(3*CIN*9*COUT) + r*COUT + tq*32;
    #pragma unroll
    for (int j = 0; j < 16; j++){
        float lo, hi; unpack2(acc2[j], lo, hi);
        wp[2*j]     = lo;
        wp[2*j + 1] = hi;
    }
}

// -------------------- launch -----------------------------------------------
extern "C" void kernel_launch(void* const* d_in, const int* in_sizes, int n_in,
                              void* d_out, int out_size)
{
    const float* input  = (const float*)d_in[0];
    const float* memory = (const float*)d_in[1];
    const float* wq     = (const float*)d_in[2];
    const float* bq     = (const float*)d_in[3];
    const float* wk     = (const float*)d_in[4];
    const float* bk     = (const float*)d_in[5];
    const float* wv     = (const float*)d_in[6];
    const float* bv     = (const float*)d_in[7];
    float* out          = (float*)d_out;

    transpose_w<<<864, 256>>>(wq, wk, wv);

    // Q+K fused: grid.z [0,8)=Q(input,bq,scale .5), [8,16)=K(memory,bk)
    conv_kernel<1><<<dim3(4, LIN, 16), 512>>>(input, memory, bq, bk, nullptr);

    gram_kernel<<<dim3(18, 2, BB), 256>>>();
    softmax_kernel<<<16*128, 128>>>(bv);
    prep_kernel<<<dim3(27, 16), 256>>>();

    // attention-folded V conv (4-row tiles): writes final output directly
    conv_kernel<3><<<dim3(8, LV, BB), 512>>>(memory, memory, bv, bv, out);
}